// round 15
// baseline (speedup 1.0000x reference)
#include <cuda_runtime.h>
#include <cuda_fp16.h>
#include <math.h>
#include <stdint.h>

#define NMAX 100000
#define EMAX 2000000

// Scratch (allocation-free rule: __device__ globals; zero-initialized at load,
// and each kernel_launch call restores the zeroed state it consumes).
__device__ int    g_deg_in [NMAX];
__device__ int    g_deg_out[NMAX];
__device__ float  g_s_out[NMAX];
__device__ float  g_s_in [NMAX];
__device__ int    g_row   [NMAX + 1];
__device__ int    g_cursor[NMAX];
__device__ int    g_esrc  [EMAX];
__device__ int    g_blk_agg [128];
__device__ int    g_blk_flag[128];
__device__ int    g_sync;
__device__ __half g_xw1h[(size_t)NMAX * 128];
__device__ __half g_xw2h[(size_t)NMAX * 64];
__device__ float  g_z   [(size_t)NMAX * 64];
__device__ __half g_rhh [(size_t)NMAX * 64];

// ---------------------------------------------------------------------------
// HMMA helper
// ---------------------------------------------------------------------------
__device__ __forceinline__ void mma16816(float* c, const uint32_t* a,
                                         uint32_t b0, uint32_t b1) {
    asm volatile(
        "mma.sync.aligned.m16n8k16.row.col.f32.f16.f16.f32 "
        "{%0,%1,%2,%3}, {%4,%5,%6,%7}, {%8,%9}, {%0,%1,%2,%3};\n"
        : "+f"(c[0]), "+f"(c[1]), "+f"(c[2]), "+f"(c[3])
        : "r"(a[0]), "r"(a[1]), "r"(a[2]), "r"(a[3]), "r"(b0), "r"(b1));
}

// ---------------------------------------------------------------------------
// Fused: degree-count (independent edge pass) + UNSCALED GEMM1.
// Blocks [0, tiles): xw1u[N,128] = [x|h] @ Wg  (fp16 out, no s_out)
// Blocks [tiles, ...): degree atomics, 4 edges/thread
// ---------------------------------------------------------------------------
#define G1_SMEM_BYTES ((128*136 + 128*136) * 2)

__global__ __launch_bounds__(256) void k_deg_gemm1(
    const float* __restrict__ x, const float* __restrict__ h,
    const float* __restrict__ Wg,
    const int* __restrict__ src, const int* __restrict__ dst,
    int n, int E, int tiles)
{
    if (blockIdx.x >= tiles) {
        int base = ((blockIdx.x - tiles) * 256 + threadIdx.x) * 4;
        if (base + 4 <= E) {
            int4 s4 = *(const int4*)(src + base);
            int4 d4 = *(const int4*)(dst + base);
            atomicAdd(&g_deg_out[s4.x], 1); atomicAdd(&g_deg_in[d4.x], 1);
            atomicAdd(&g_deg_out[s4.y], 1); atomicAdd(&g_deg_in[d4.y], 1);
            atomicAdd(&g_deg_out[s4.z], 1); atomicAdd(&g_deg_in[d4.z], 1);
            atomicAdd(&g_deg_out[s4.w], 1); atomicAdd(&g_deg_in[d4.w], 1);
        } else {
            for (int e = base; e < E; e++) {
                atomicAdd(&g_deg_out[src[e]], 1);
                atomicAdd(&g_deg_in [dst[e]], 1);
            }
        }
        return;
    }

    extern __shared__ __half sh[];
    __half* Ash = sh;                 // [128][136]
    __half* Wsh = sh + 128 * 136;     // [128][136]  (row = n, col = k)
    int t = threadIdx.x;
    int row0 = blockIdx.x * 128;

    for (int it = t; it < 128 * 32; it += 256) {
        int m = it >> 5, q = it & 31;
        int gr = row0 + m;
        float4 v = make_float4(0.f, 0.f, 0.f, 0.f);
        if (gr < n) {
            const float* srcp = (q < 16) ? (x + (size_t)gr * 64 + q * 4)
                                         : (h + (size_t)gr * 64 + (q - 16) * 4);
            v = *(const float4*)srcp;
        }
        __half2 p0 = __floats2half2_rn(v.x, v.y);
        __half2 p1 = __floats2half2_rn(v.z, v.w);
        *(uint2*)(Ash + m * 136 + q * 4) = make_uint2(*(unsigned*)&p0, *(unsigned*)&p1);
    }
    for (int it = t; it < 128 * 32; it += 256) {
        int k = it >> 5, q = it & 31;
        float4 v = *(const float4*)(Wg + (size_t)k * 128 + q * 4);
        Wsh[(q * 4 + 0) * 136 + k] = __float2half(v.x);
        Wsh[(q * 4 + 1) * 136 + k] = __float2half(v.y);
        Wsh[(q * 4 + 2) * 136 + k] = __float2half(v.z);
        Wsh[(q * 4 + 3) * 136 + k] = __float2half(v.w);
    }
    __syncthreads();

    int wid = t >> 5, lane = t & 31;
    int gp = lane >> 2, tg = lane & 3;
    int wm = (wid >> 1) * 32, wn = (wid & 1) * 64;

    float acc[2][8][4];
#pragma unroll
    for (int mi = 0; mi < 2; mi++)
#pragma unroll
        for (int ni = 0; ni < 8; ni++)
#pragma unroll
            for (int j = 0; j < 4; j++) acc[mi][ni][j] = 0.f;

#pragma unroll
    for (int k0 = 0; k0 < 128; k0 += 16) {
        uint32_t a[2][4];
#pragma unroll
        for (int mi = 0; mi < 2; mi++) {
            int r = wm + mi * 16 + gp;
            a[mi][0] = *(uint32_t*)(Ash + r * 136 + k0 + tg * 2);
            a[mi][1] = *(uint32_t*)(Ash + (r + 8) * 136 + k0 + tg * 2);
            a[mi][2] = *(uint32_t*)(Ash + r * 136 + k0 + 8 + tg * 2);
            a[mi][3] = *(uint32_t*)(Ash + (r + 8) * 136 + k0 + 8 + tg * 2);
        }
#pragma unroll
        for (int ni = 0; ni < 8; ni++) {
            int c = wn + ni * 8 + gp;
            uint32_t b0 = *(uint32_t*)(Wsh + c * 136 + k0 + tg * 2);
            uint32_t b1 = *(uint32_t*)(Wsh + c * 136 + k0 + 8 + tg * 2);
            mma16816(acc[0][ni], a[0], b0, b1);
            mma16816(acc[1][ni], a[1], b0, b1);
        }
    }

#pragma unroll
    for (int mi = 0; mi < 2; mi++) {
        int r = row0 + wm + mi * 16 + gp;
#pragma unroll
        for (int ni = 0; ni < 8; ni++) {
            int c = wn + ni * 8 + tg * 2;
            if (r < n) {
                __half2 p = __floats2half2_rn(acc[mi][ni][0], acc[mi][ni][1]);
                *(unsigned*)(g_xw1h + (size_t)r * 128 + c) = *(unsigned*)&p;
            }
            if (r + 8 < n) {
                __half2 p = __floats2half2_rn(acc[mi][ni][2], acc[mi][ni][3]);
                *(unsigned*)(g_xw1h + (size_t)(r + 8) * 128 + c) = *(unsigned*)&p;
            }
        }
    }
}

// ---------------------------------------------------------------------------
// Single-pass scan (decoupled lookback) + in-place s_out scaling of xw1h
// + global barrier + bucket scatter.
// <=98 blocks of 1024 threads — all co-resident, so spins are safe.
// ---------------------------------------------------------------------------
__global__ __launch_bounds__(1024) void k_scan_bucket(
    const int* __restrict__ src, const int* __restrict__ dst, int n, int E)
{
    int b = blockIdx.x, t = threadIdx.x;
    int i = b * 1024 + t;
    int v = (i < n) ? g_deg_in[i] : 0;
    int lane = t & 31, wid = t >> 5;

    int inc = v;
    for (int o = 1; o < 32; o <<= 1) {
        int u = __shfl_up_sync(~0u, inc, o);
        if (lane >= o) inc += u;
    }
    __shared__ int ws[32];
    if (lane == 31) ws[wid] = inc;
    __syncthreads();
    if (t < 32) {
        int u = ws[t];
        for (int o = 1; o < 32; o <<= 1) {
            int w = __shfl_up_sync(~0u, u, o);
            if (t >= o) u += w;
        }
        ws[t] = u;
    }
    __syncthreads();
    int block_incl = inc + (wid ? ws[wid - 1] : 0);
    int total = ws[31];

    if (t == 0) {
        g_blk_agg[b] = total;
        __threadfence();
        *((volatile int*)&g_blk_flag[b]) = 1;
    }

    __shared__ int s_prefix;
    if (wid == 0) {
        int sum = 0;
        for (int p = lane; p < b; p += 32) {
            while (*((volatile int*)&g_blk_flag[p]) == 0) { }
            sum += *((volatile int*)&g_blk_agg[p]);
        }
        for (int o = 16; o > 0; o >>= 1) sum += __shfl_down_sync(~0u, sum, o);
        if (lane == 0) s_prefix = sum;
    }
    __syncthreads();

    int excl = s_prefix + block_incl - v;
    if (i < n) {
        g_row[i]    = excl;
        g_cursor[i] = excl;
        g_s_in [i]  = rsqrtf(fmaxf((float)v, 1.f));
        g_s_out[i]  = rsqrtf(fmaxf((float)g_deg_out[i], 1.f));
        if (i == n - 1) g_row[n] = excl + v;
    }
    __syncthreads();   // s_out for this block's 1024 rows is now visible

    // ---- scale xw1h rows of this block's nodes by s_out (coalesced) ----
    {
        int rbase = b * 1024 + wid * 32;
#pragma unroll 4
        for (int r0 = 0; r0 < 32; r0++) {
            int r = rbase + r0;
            if (r < n) {
                __half2 s2 = __float2half2_rn(g_s_out[r]);
                uint2* rp = (uint2*)(g_xw1h + (size_t)r * 128) + lane;
                uint2 u = *rp;
                ((__half2*)&u)[0] = __hmul2(((__half2*)&u)[0], s2);
                ((__half2*)&u)[1] = __hmul2(((__half2*)&u)[1], s2);
                *rp = u;
            }
        }
    }

    // ---- global barrier (all blocks co-resident) ----
    __syncthreads();
    if (t == 0) {
        __threadfence();
        atomicAdd(&g_sync, 1);
        while (*((volatile int*)&g_sync) < gridDim.x) { }
    }
    __syncthreads();
    __threadfence();

    // ---- bucket scatter, grid-stride ----
    int stride = gridDim.x * 1024;
    for (int e = b * 1024 + t; e < E; e += stride) {
        int p = atomicAdd(&g_cursor[dst[e]], 1);
        g_esrc[p] = src[e];
    }
}

// ---------------------------------------------------------------------------
// Agg1 + gates fused: warp per node; xw1h pre-scaled; pairwise HADD2.
// Also resets barrier state for the next call (block 0).
// ---------------------------------------------------------------------------
__global__ __launch_bounds__(256) void k_agg1_gates(
    const float* __restrict__ h, const float* __restrict__ bg, int n)
{
    int gt = blockIdx.x * blockDim.x + threadIdx.x;
    if (gt == 0) {
        g_sync = 0;
#pragma unroll 4
        for (int j = 0; j < 128; j++) g_blk_flag[j] = 0;
    }
    int i = gt >> 5;
    if (i >= n) return;
    int lane = gt & 31;

    int p   = g_row[i];
    int end = g_row[i + 1];
    float4 acc = make_float4(0.f, 0.f, 0.f, 0.f);

    for (; p + 8 <= end; p += 8) {
        int s[8];
#pragma unroll
        for (int j = 0; j < 8; j++) s[j] = __ldg(g_esrc + p + j);
        uint2 u[8];
#pragma unroll
        for (int j = 0; j < 8; j++)
            u[j] = __ldg((const uint2*)(g_xw1h + (size_t)s[j] * 128) + lane);
#pragma unroll
        for (int k = 0; k < 4; k++) {
            __half2 sx = __hadd2(*(__half2*)&u[2*k].x, *(__half2*)&u[2*k+1].x);
            __half2 sy = __hadd2(*(__half2*)&u[2*k].y, *(__half2*)&u[2*k+1].y);
            float2 fx = __half22float2(sx), fy = __half22float2(sy);
            acc.x += fx.x; acc.y += fx.y; acc.z += fy.x; acc.w += fy.y;
        }
    }
    if (p + 4 <= end) {
        int s[4];
#pragma unroll
        for (int j = 0; j < 4; j++) s[j] = __ldg(g_esrc + p + j);
        uint2 u[4];
#pragma unroll
        for (int j = 0; j < 4; j++)
            u[j] = __ldg((const uint2*)(g_xw1h + (size_t)s[j] * 128) + lane);
#pragma unroll
        for (int k = 0; k < 2; k++) {
            __half2 sx = __hadd2(*(__half2*)&u[2*k].x, *(__half2*)&u[2*k+1].x);
            __half2 sy = __hadd2(*(__half2*)&u[2*k].y, *(__half2*)&u[2*k+1].y);
            float2 fx = __half22float2(sx), fy = __half22float2(sy);
            acc.x += fx.x; acc.y += fx.y; acc.z += fy.x; acc.w += fy.y;
        }
        p += 4;
    }
    for (; p < end; p++) {
        int s0 = __ldg(g_esrc + p);
        uint2 u0 = __ldg((const uint2*)(g_xw1h + (size_t)s0 * 128) + lane);
        float2 a0 = __half22float2(*(__half2*)&u0.x), b0 = __half22float2(*(__half2*)&u0.y);
        acc.x += a0.x; acc.y += a0.y; acc.z += b0.x; acc.w += b0.y;
    }

    float si = g_s_in[i];
    float4 b4 = __ldg((const float4*)bg + lane);
    float4 g;
    g.x = 1.f / (1.f + expf(-(acc.x * si + b4.x)));
    g.y = 1.f / (1.f + expf(-(acc.y * si + b4.y)));
    g.z = 1.f / (1.f + expf(-(acc.z * si + b4.z)));
    g.w = 1.f / (1.f + expf(-(acc.w * si + b4.w)));

    if (lane < 16) {
        float4 h4 = __ldg((const float4*)(h + (size_t)i * 64) + lane);
        __half2 r0 = __floats2half2_rn(g.x * h4.x, g.y * h4.y);
        __half2 r1 = __floats2half2_rn(g.z * h4.z, g.w * h4.w);
        *((uint2*)(g_rhh + (size_t)i * 64) + lane) =
            make_uint2(*(unsigned*)&r0, *(unsigned*)&r1);
    } else {
        *((float4*)(g_z + (size_t)i * 64) + (lane - 16)) = g;
    }
}

// ---------------------------------------------------------------------------
// GEMM2 (HMMA): xw2[N,64] = diag(s_out) * ([x|rh] @ Wc[128,64])  (fp16 out)
// s_out applied at output (available by now). rh already fp16.
// ---------------------------------------------------------------------------
#define G2_SMEM_BYTES ((128*136 + 64*136) * 2)

__global__ __launch_bounds__(256) void k_gemm2(
    const float* __restrict__ x, const float* __restrict__ Wc, int n)
{
    extern __shared__ __half sh[];
    __half* Ash = sh;               // [128][136]
    __half* Wsh = sh + 128 * 136;   // [64][136]
    int t = threadIdx.x;
    int row0 = blockIdx.x * 128;

    for (int it = t; it < 128 * 32; it += 256) {
        int m = it >> 5, q = it & 31;
        int gr = row0 + m;
        uint2 u = make_uint2(0u, 0u);
        if (gr < n) {
            if (q < 16) {
                float4 v = *(const float4*)(x + (size_t)gr * 64 + q * 4);
                __half2 p0 = __floats2half2_rn(v.x, v.y);
                __half2 p1 = __floats2half2_rn(v.z, v.w);
                u = make_uint2(*(unsigned*)&p0, *(unsigned*)&p1);
            } else {
                u = *(const uint2*)(g_rhh + (size_t)gr * 64 + (q - 16) * 4);
            }
        }
        *(uint2*)(Ash + m * 136 + q * 4) = u;
    }
    for (int it = t; it < 128 * 16; it += 256) {
        int k = it >> 4, q = it & 15;
        float4 v = *(const float4*)(Wc + (size_t)k * 64 + q * 4);
        Wsh[(q * 4 + 0) * 136 + k] = __float2half(v.x);
        Wsh[(q * 4 + 1) * 136 + k] = __float2half(v.y);
        Wsh[(q * 4 + 2) * 136 + k] = __float2half(v.z);
        Wsh[(q * 4 + 3) * 136 + k] = __float2half(v.w);
    }
    __syncthreads();

    int wid = t >> 5, lane = t & 31;
    int gp = lane >> 2, tg = lane & 3;
    int wm = wid * 16;

    float acc[8][4];
#pragma unroll
    for (int ni = 0; ni < 8; ni++)
#pragma unroll
        for (int j = 0; j < 4; j++) acc[ni][j] = 0.f;

#pragma unroll
    for (int k0 = 0; k0 < 128; k0 += 16) {
        uint32_t a[4];
        int r = wm + gp;
        a[0] = *(uint32_t*)(Ash + r * 136 + k0 + tg * 2);
        a[1] = *(uint32_t*)(Ash + (r + 8) * 136 + k0 + tg * 2);
        a[2] = *(uint32_t*)(Ash + r * 136 + k0 + 8 + tg * 2);
        a[3] = *(uint32_t*)(Ash + (r + 8) * 136 + k0 + 8 + tg * 2);
#pragma unroll
        for (int ni = 0; ni < 8; ni++) {
            int c = ni * 8 + gp;
            uint32_t b0 = *(uint32_t*)(Wsh + c * 136 + k0 + tg * 2);
            uint32_t b1 = *(uint32_t*)(Wsh + c * 136 + k0 + 8 + tg * 2);
            mma16816(acc[ni], a, b0, b1);
        }
    }

    int r = row0 + wm + gp;
    float so0 = (r     < n) ? g_s_out[r]     : 0.f;
    float so1 = (r + 8 < n) ? g_s_out[r + 8] : 0.f;
#pragma unroll
    for (int ni = 0; ni < 8; ni++) {
        int c = ni * 8 + tg * 2;
        if (r < n) {
            __half2 p = __floats2half2_rn(acc[ni][0] * so0, acc[ni][1] * so0);
            *(unsigned*)(g_xw2h + (size_t)r * 64 + c) = *(unsigned*)&p;
        }
        if (r + 8 < n) {
            __half2 p = __floats2half2_rn(acc[ni][2] * so1, acc[ni][3] * so1);
            *(unsigned*)(g_xw2h + (size_t)(r + 8) * 64 + c) = *(unsigned*)&p;
        }
    }
}

// ---------------------------------------------------------------------------
// Agg2 + GRU epilogue fused: 16 lanes per node; xw2h pre-scaled; HADD2 pairs.
// Also re-zeroes degree counters for the next call.
// ---------------------------------------------------------------------------
__global__ __launch_bounds__(256) void k_agg2_final(
    const float* __restrict__ h, const float* __restrict__ bc,
    float* __restrict__ out, int n)
{
    int gt = blockIdx.x * blockDim.x + threadIdx.x;
    if (gt < n) { g_deg_in[gt] = 0; g_deg_out[gt] = 0; }
    int i = gt >> 4;
    if (i >= n) return;
    int q = gt & 15;

    int p   = g_row[i];
    int end = g_row[i + 1];
    float4 acc = make_float4(0.f, 0.f, 0.f, 0.f);

    for (; p + 8 <= end; p += 8) {
        int s[8];
#pragma unroll
        for (int j = 0; j < 8; j++) s[j] = __ldg(g_esrc + p + j);
        uint2 u[8];
#pragma unroll
        for (int j = 0; j < 8; j++)
            u[j] = __ldg((const uint2*)(g_xw2h + (size_t)s[j] * 64) + q);
#pragma unroll
        for (int k = 0; k < 4; k++) {
            __half2 sx = __hadd2(*(__half2*)&u[2*k].x, *(__half2*)&u[2*k+1].x);
            __half2 sy = __hadd2(*(__half2*)&u[2*k].y, *(__half2*)&u[2*k+1].y);
            float2 fx = __half22float2(sx), fy = __half22float2(sy);
            acc.x += fx.x; acc.y += fx.y; acc.z += fy.x; acc.w += fy.y;
        }
    }
    if (p + 4 <= end) {
        int s[4];
#pragma unroll
        for (int j = 0; j < 4; j++) s[j] = __ldg(g_esrc + p + j);
        uint2 u[4];
#pragma unroll
        for (int j = 0; j < 4; j++)
            u[j] = __ldg((const uint2*)(g_xw2h + (size_t)s[j] * 64) + q);
#pragma unroll
        for (int k = 0; k < 2; k++) {
            __half2 sx = __hadd2(*(__half2*)&u[2*k].x, *(__half2*)&u[2*k+1].x);
            __half2 sy = __hadd2(*(__half2*)&u[2*k].y, *(__half2*)&u[2*k+1].y);
            float2 fx = __half22float2(sx), fy = __half22float2(sy);
            acc.x += fx.x; acc.y += fx.y; acc.z += fy.x; acc.w += fy.y;
        }
        p += 4;
    }
    for (; p < end; p++) {
        int s0 = __ldg(g_esrc + p);
        uint2 u0 = __ldg((const uint2*)(g_xw2h + (size_t)s0 * 64) + q);
        float2 a0 = __half22float2(*(__half2*)&u0.x), b0 = __half22float2(*(__half2*)&u0.y);
        acc.x += a0.x; acc.y += a0.y; acc.z += b0.x; acc.w += b0.y;
    }

    float si = g_s_in[i];
    float4 b4 = __ldg((const float4*)bc + q);
    float4 z4 = *((const float4*)(g_z + (size_t)i * 64) + q);
    float4 h4 = __ldg((const float4*)(h + (size_t)i * 64) + q);
    float4 o;
    o.x = z4.x * h4.x + (1.f - z4.x) * tanhf(acc.x * si + b4.x);
    o.y = z4.y * h4.y + (1.f - z4.y) * tanhf(acc.y * si + b4.y);
    o.z = z4.z * h4.z + (1.f - z4.z) * tanhf(acc.z * si + b4.z);
    o.w = z4.w * h4.w + (1.f - z4.w) * tanhf(acc.w * si + b4.w);
    *((float4*)(out + (size_t)i * 64) + q) = o;
}

// ---------------------------------------------------------------------------
extern "C" void kernel_launch(void* const* d_in, const int* in_sizes, int n_in,
                              void* d_out, int out_size)
{
    const float* x   = (const float*)d_in[0];
    const float* h   = (const float*)d_in[1];
    const int*   src = (const int*)  d_in[2];
    const int*   dst = (const int*)  d_in[3];
    const float* Wg  = (const float*)d_in[4];
    const float* bg  = (const float*)d_in[5];
    const float* Wc  = (const float*)d_in[6];
    const float* bc  = (const float*)d_in[7];
    float* out = (float*)d_out;

    int n = in_sizes[0] / 64;
    int E = in_sizes[2];
    int NB = (n + 1023) / 1024;

    cudaFuncSetAttribute(k_deg_gemm1, cudaFuncAttributeMaxDynamicSharedMemorySize, G1_SMEM_BYTES);
    cudaFuncSetAttribute(k_gemm2,     cudaFuncAttributeMaxDynamicSharedMemorySize, G2_SMEM_BYTES);

    int tiles = (n + 127) / 128;
    int degB = (E + 1023) / 1024;   // 4 edges/thread, 256 threads
    k_deg_gemm1<<<tiles + degB, 256, G1_SMEM_BYTES>>>(x, h, Wg, src, dst, n, E, tiles);

    k_scan_bucket<<<NB, 1024>>>(src, dst, n, E);

    int nb;
    nb = (int)(((long long)n * 32 + 255) / 256);
    k_agg1_gates<<<nb, 256>>>(h, bg, n);

    k_gemm2<<<tiles, 256, G2_SMEM_BYTES>>>(x, Wc, n);

    nb = (int)(((long long)n * 16 + 255) / 256);
    k_agg2_final<<<nb, 256>>>(h, bc, out, n);
}